// round 8
// baseline (speedup 1.0000x reference)
#include <cuda_runtime.h>
#include <cstdint>

#define FULLMASK 0xFFFFFFFFu

// ---------------------------------------------------------------------------
__device__ int g_is64;

// Detect whether ids buffer is int64 (LE: high words all zero for values<512)
// or int32 (odd words random ids, ~never all zero across 1024 samples).
__global__ void k_detect(const unsigned* __restrict__ w, int npairs) {
    __shared__ int any;
    if (threadIdx.x == 0) any = 0;
    __syncthreads();
    int found = 0;
    for (int i = threadIdx.x; i < npairs; i += blockDim.x)
        found |= (w[2 * i + 1] != 0u);
    if (found) any = 1;   // benign race: same value
    __syncthreads();
    if (threadIdx.x == 0) g_is64 = (any ? 0 : 1);
}

// ---------------------------------------------------------------------------
// Main kernel: one warp per batch row.
//   e-mapping: element e = k*128 + lane*4 + j  (k 0..3, j 0..3)
// FP-order emulation of reference (scatter-add -> dense @ cooc):
//   duplicates combined first; ascending-id fused-FMA accumulation.
// Top-32 select: 8 bisection halvings on float bits, then compact the
//   boundary window and finish exactly (value desc, index asc ties).
// ---------------------------------------------------------------------------
constexpr int WARPS = 4;

__global__ __launch_bounds__(128, 10)
void k_main(const void* __restrict__ idsraw,
            const float* __restrict__ scores,
            const float* __restrict__ cooc,
            void* __restrict__ outp, int B, int mode)
{
    __shared__ unsigned sbm[WARPS][16];    // 512-bit candidate bitmap per row
    __shared__ float    sval[WARPS][32];
    __shared__ int      sidx[WARPS][32];
    __shared__ unsigned swin_u[WARPS][64]; // boundary-window values
    __shared__ int      swin_e[WARPS][64]; // boundary-window indices

    const int warp = threadIdx.x >> 5;
    const int lane = threadIdx.x & 31;
    const long long b = (long long)blockIdx.x * WARPS + warp;
    if (b >= B) return;

    const int is64 = g_is64;
    int myid;
    if (is64) myid = (int)((const long long*)idsraw)[b * 32 + lane];
    else      myid = ((const int*)idsraw)[b * 32 + lane];
    const float mys = scores[b * 32 + lane];

    if (lane < 16) sbm[warp][lane] = 0u;
    __syncwarp();
    atomicOr(&sbm[warp][myid >> 5], 1u << (myid & 31));

    // ---- stable sort (id asc, occurrence asc) via bitonic on unique key ---
    int   skey = (myid << 5) | lane;     // unique -> stable
    float ssv  = mys;
    #pragma unroll
    for (int k = 2; k <= 32; k <<= 1) {
        #pragma unroll
        for (int j = k >> 1; j > 0; j >>= 1) {
            int   ok = __shfl_xor_sync(FULLMASK, skey, j);
            float os = __shfl_xor_sync(FULLMASK, ssv,  j);
            bool lower  = (lane & j) == 0;
            bool dirAsc = (lane & k) == 0;
            bool takeOther = (dirAsc == lower) ? (ok < skey) : (ok > skey);
            if (takeOther) { skey = ok; ssv = os; }
        }
    }
    const int sid = skey >> 5;           // ids ascending across lanes

    // ---- segmented inclusive scan: combine duplicate ids ------------------
    #pragma unroll
    for (int off = 1; off < 32; off <<= 1) {
        float up  = __shfl_up_sync(FULLMASK, ssv, off);
        int   uid = __shfl_up_sync(FULLMASK, sid, off);
        if (lane >= off && uid == sid) ssv += up;
    }
    int nid = __shfl_down_sync(FULLMASK, sid, 1);
    bool tail = (lane == 31) || (nid != sid);
    const float fs = tail ? ssv : 0.0f;  // fmaf(0,c,a)==a exactly

    // -------------------- sparse gather-accumulate (id-ascending) ---------
    float a[16];
    #pragma unroll
    for (int j = 0; j < 16; ++j) a[j] = 0.f;

    const float4* base4 = (const float4*)cooc;
    #pragma unroll 4
    for (int i = 0; i < 32; ++i) {
        int   id = __shfl_sync(FULLMASK, sid, i);
        float s  = __shfl_sync(FULLMASK, fs,  i);
        const float4* r = base4 + (size_t)id * 128 + lane;
        float4 c0 = __ldg(r);
        float4 c1 = __ldg(r + 32);
        float4 c2 = __ldg(r + 64);
        float4 c3 = __ldg(r + 96);
        a[ 0] = fmaf(s, c0.x, a[ 0]); a[ 1] = fmaf(s, c0.y, a[ 1]);
        a[ 2] = fmaf(s, c0.z, a[ 2]); a[ 3] = fmaf(s, c0.w, a[ 3]);
        a[ 4] = fmaf(s, c1.x, a[ 4]); a[ 5] = fmaf(s, c1.y, a[ 5]);
        a[ 6] = fmaf(s, c1.z, a[ 6]); a[ 7] = fmaf(s, c1.w, a[ 7]);
        a[ 8] = fmaf(s, c2.x, a[ 8]); a[ 9] = fmaf(s, c2.y, a[ 9]);
        a[10] = fmaf(s, c2.z, a[10]); a[11] = fmaf(s, c2.w, a[11]);
        a[12] = fmaf(s, c3.x, a[12]); a[13] = fmaf(s, c3.y, a[13]);
        a[14] = fmaf(s, c3.z, a[14]); a[15] = fmaf(s, c3.w, a[15]);
    }
    __syncwarp();

    // -------------------- mask candidates (key = 0) -----------------------
    // All sums strictly positive -> float bits order-preserving as unsigned.
    unsigned ue[16];
    #pragma unroll
    for (int k = 0; k < 4; ++k) {
        unsigned wbits = sbm[warp][k * 4 + (lane >> 3)];
        unsigned sh = (lane & 7) * 4;
        #pragma unroll
        for (int j = 0; j < 4; ++j) {
            bool masked = (wbits >> (sh + j)) & 1u;
            ue[k * 4 + j] = masked ? 0u : __float_as_uint(a[k * 4 + j]);
        }
    }

    // -------------------- warp max key ------------------------------------
    unsigned mk = 0;
    #pragma unroll
    for (int j = 0; j < 16; ++j) mk = max(mk, ue[j]);
    #pragma unroll
    for (int o = 16; o > 0; o >>= 1)
        mk = max(mk, __shfl_xor_sync(FULLMASK, mk, o));

    // -------------------- chunked bisection + window compaction -----------
    // invariants: count(>lo) > 32 (lo=0: 480), count(>hi) < 32 (hi=mk: 0)
    unsigned lo = 0, hi = mk, T = 0;
    bool exact = false;
    int m = 0;          // winners > hi (same value in all lanes)
    int W = 0;          // window entries in (lo, hi]
    int chunks = 0;

    for (;;) {
        #pragma unroll 1
        for (int it = 0; it < 8 && (hi - lo > 1u); ++it) {
            unsigned mid = lo + ((hi - lo) >> 1);
            int c = 0;
            #pragma unroll
            for (int j = 0; j < 16; ++j) c += (ue[j] > mid);
            c = __reduce_add_sync(FULLMASK, c);
            if (c == 32) { T = mid; exact = true; break; }
            if (c > 32) lo = mid; else hi = mid;
        }
        if (exact) break;

        // compact: winners (> hi) and window ((lo, hi]) via ballot prefix
        unsigned lmask = (1u << lane) - 1u;
        int base = 0, wbase = 0;
        #pragma unroll
        for (int k = 0; k < 4; ++k)
            #pragma unroll
            for (int j = 0; j < 4; ++j) {
                unsigned u = ue[k * 4 + j];
                int e = k * 128 + lane * 4 + j;
                bool win = (u > hi);
                bool mid = (u > lo) && !win;
                unsigned bw = __ballot_sync(FULLMASK, win);
                unsigned bm = __ballot_sync(FULLMASK, mid);
                if (win) {
                    int p = base + __popc(bw & lmask);
                    sval[warp][p] = __uint_as_float(u);
                    sidx[warp][p] = e;
                }
                if (mid) {
                    int q = wbase + __popc(bm & lmask);
                    if (q < 64) { swin_u[warp][q] = u; swin_e[warp][q] = e; }
                }
                base  += __popc(bw);
                wbase += __popc(bm);
            }
        m = base; W = wbase;
        if (W <= 64 || hi - lo <= 1u || ++chunks >= 5) break;
        // window too large -> narrow further and recompact
    }

    if (exact) {
        // exactly 32 values > T: compact them
        unsigned lmask = (1u << lane) - 1u;
        int base = 0;
        #pragma unroll
        for (int k = 0; k < 4; ++k)
            #pragma unroll
            for (int j = 0; j < 4; ++j) {
                unsigned u = ue[k * 4 + j];
                bool win = (u > T);
                unsigned bw = __ballot_sync(FULLMASK, win);
                if (win) {
                    int p = base + __popc(bw & lmask);
                    sval[warp][p] = __uint_as_float(u);
                    sidx[warp][p] = k * 128 + lane * 4 + j;
                }
                base += __popc(bw);
            }
        __syncwarp();
    } else {
        // fill remaining 32-m from window: largest value first, ties by
        // smallest index (jax top_k order). W is tiny in expectation.
        __syncwarp();
        int need = 32 - m;
        int Wc = min(W, 64);
        if (lane == 0) {
            for (int t = 0; t < need; ++t) {
                unsigned bu = 0; int be = 0x7FFFFFFF, bj = -1;
                for (int j2 = 0; j2 < Wc; ++j2) {
                    unsigned u2 = swin_u[warp][j2];
                    int e2 = swin_e[warp][j2];
                    if (u2 > bu || (u2 == bu && u2 != 0u && e2 < be)) {
                        bu = u2; be = e2; bj = j2;
                    }
                }
                sval[warp][m + t] = __uint_as_float(bu);
                sidx[warp][m + t] = be;
                if (bj >= 0) swin_u[warp][bj] = 0u;
            }
        }
        __syncwarp();
    }

    float v = sval[warp][lane];
    int   e = sidx[warp][lane];

    // -------------------- bitonic sort 32 (desc value, asc index) ---------
    #pragma unroll
    for (int k = 2; k <= 32; k <<= 1) {
        #pragma unroll
        for (int j = k >> 1; j > 0; j >>= 1) {
            float ov = __shfl_xor_sync(FULLMASK, v, j);
            int   oe = __shfl_xor_sync(FULLMASK, e, j);
            bool lower   = (lane & j) == 0;
            bool dirDesc = (lane & k) == 0;
            bool otherBetter = (ov > v) || (ov == v && oe < e);
            bool take = (dirDesc == lower) ? otherBetter : !otherBetter;
            if (take) { v = ov; e = oe; }
        }
    }

    // -------------------- write output ------------------------------------
    const long long n = (long long)B * 64;
    if (mode == 0) {
        float* o = (float*)outp;
        o[b * 64 + lane]          = (float)myid;
        o[b * 64 + 32 + lane]     = (float)e;
        o[n + b * 64 + lane]      = mys;
        o[n + b * 64 + 32 + lane] = v;
    } else if (mode == 1) {
        long long* oid = (long long*)outp;
        float* osc = (float*)((char*)outp + n * 8);
        oid[b * 64 + lane]      = (long long)myid;
        oid[b * 64 + 32 + lane] = (long long)e;
        osc[b * 64 + lane]      = mys;
        osc[b * 64 + 32 + lane] = v;
    } else if (mode == 2) {
        int* oid = (int*)outp;
        float* osc = (float*)((char*)outp + n * 4);
        oid[b * 64 + lane]      = myid;
        oid[b * 64 + 32 + lane] = e;
        osc[b * 64 + lane]      = mys;
        osc[b * 64 + 32 + lane] = v;
    } else {
        double* o = (double*)outp;
        o[b * 64 + lane]          = (double)myid;
        o[b * 64 + 32 + lane]     = (double)e;
        o[n + b * 64 + lane]      = (double)mys;
        o[n + b * 64 + 32 + lane] = (double)v;
    }
}

// ---------------------------------------------------------------------------
extern "C" void kernel_launch(void* const* d_in, const int* in_sizes, int n_in,
                              void* d_out, int out_size) {
    const void*  ids    = d_in[0];
    const float* scores = (const float*)d_in[1];
    const float* cooc   = (const float*)d_in[2];

    const int B = in_sizes[0] / 32;
    const long long n = (long long)B * 64;
    const long long S = (long long)out_size;

    int mode;
    if      (S == 2 * n)                                  mode = 0; // f32 concat
    else if (S == 3 * n || S == 12 * n || 2 * S == 3 * n) mode = 1; // i64+f32 raw
    else if (S == 8 * n)                                  mode = 2; // i32+f32 raw
    else if (S == 4 * n)                                  mode = 3; // f64 concat
    else                                                  mode = 0; // safest

    k_detect<<<1, 128>>>((const unsigned*)ids, 1024);
    k_main<<<(B + WARPS - 1) / WARPS, 128>>>(ids, scores, cooc, d_out, B, mode);
}

// round 9
// speedup vs baseline: 1.2176x; 1.2176x over previous
#include <cuda_runtime.h>
#include <cstdint>

#define FULLMASK 0xFFFFFFFFu

// ---------------------------------------------------------------------------
__device__ int g_is64;

// Detect whether ids buffer is int64 (LE: high words all zero for values<512)
// or int32 (odd words random ids, ~never all zero across 1024 samples).
__global__ void k_detect(const unsigned* __restrict__ w, int npairs) {
    __shared__ int any;
    if (threadIdx.x == 0) any = 0;
    __syncthreads();
    int found = 0;
    for (int i = threadIdx.x; i < npairs; i += blockDim.x)
        found |= (w[2 * i + 1] != 0u);
    if (found) any = 1;   // benign race: same value
    __syncthreads();
    if (threadIdx.x == 0) g_is64 = (any ? 0 : 1);
}

// ---------------------------------------------------------------------------
// Main kernel: one warp per batch row.
//   e-mapping: element e = k*128 + lane*4 + j  (k 0..3, j 0..3)
// FP-order emulation of reference (scatter-add -> dense @ cooc):
//   duplicates combined first; ascending-id fused-FMA accumulation.
// Top-32 select: Illinois regula-falsi on float-interpreted keys (exact
//   uint threshold; ~6 iterations instead of ~30 blind bisections).
// ---------------------------------------------------------------------------
constexpr int WARPS = 4;

__global__ __launch_bounds__(128, 10)
void k_main(const void* __restrict__ idsraw,
            const float* __restrict__ scores,
            const float* __restrict__ cooc,
            void* __restrict__ outp, int B, int mode)
{
    __shared__ unsigned sbm[WARPS][16];   // 512-bit candidate bitmap per row
    __shared__ float    sval[WARPS][32];
    __shared__ int      sidx[WARPS][32];
    __shared__ int      scnt[WARPS];
    __shared__ int      seqcnt[WARPS];
    __shared__ int      seqe[WARPS][64];

    const int warp = threadIdx.x >> 5;
    const int lane = threadIdx.x & 31;
    const long long b = (long long)blockIdx.x * WARPS + warp;
    if (b >= B) return;

    const int is64 = g_is64;
    int myid;
    if (is64) myid = (int)((const long long*)idsraw)[b * 32 + lane];
    else      myid = ((const int*)idsraw)[b * 32 + lane];
    const float mys = scores[b * 32 + lane];

    if (lane < 16) sbm[warp][lane] = 0u;
    if (lane == 0) { scnt[warp] = 0; seqcnt[warp] = 0; }
    __syncwarp();
    atomicOr(&sbm[warp][myid >> 5], 1u << (myid & 31));

    // ---- stable sort (id asc, occurrence asc) via bitonic on unique key ---
    int   skey = (myid << 5) | lane;     // unique -> stable
    float ssv  = mys;
    #pragma unroll
    for (int k = 2; k <= 32; k <<= 1) {
        #pragma unroll
        for (int j = k >> 1; j > 0; j >>= 1) {
            int   ok = __shfl_xor_sync(FULLMASK, skey, j);
            float os = __shfl_xor_sync(FULLMASK, ssv,  j);
            bool lower  = (lane & j) == 0;
            bool dirAsc = (lane & k) == 0;
            bool takeOther = (dirAsc == lower) ? (ok < skey) : (ok > skey);
            if (takeOther) { skey = ok; ssv = os; }
        }
    }
    const int sid = skey >> 5;           // ids ascending across lanes

    // ---- segmented inclusive scan: combine duplicate ids ------------------
    #pragma unroll
    for (int off = 1; off < 32; off <<= 1) {
        float up  = __shfl_up_sync(FULLMASK, ssv, off);
        int   uid = __shfl_up_sync(FULLMASK, sid, off);
        if (lane >= off && uid == sid) ssv += up;
    }
    int nid = __shfl_down_sync(FULLMASK, sid, 1);
    bool tail = (lane == 31) || (nid != sid);
    const float fs = tail ? ssv : 0.0f;  // fmaf(0,c,a)==a exactly

    // -------------------- sparse gather-accumulate (id-ascending) ---------
    float a[16];
    #pragma unroll
    for (int j = 0; j < 16; ++j) a[j] = 0.f;

    const float4* base4 = (const float4*)cooc;
    #pragma unroll 4
    for (int i = 0; i < 32; ++i) {
        int   id = __shfl_sync(FULLMASK, sid, i);
        float s  = __shfl_sync(FULLMASK, fs,  i);
        const float4* r = base4 + (size_t)id * 128 + lane;
        float4 c0 = __ldg(r);
        float4 c1 = __ldg(r + 32);
        float4 c2 = __ldg(r + 64);
        float4 c3 = __ldg(r + 96);
        a[ 0] = fmaf(s, c0.x, a[ 0]); a[ 1] = fmaf(s, c0.y, a[ 1]);
        a[ 2] = fmaf(s, c0.z, a[ 2]); a[ 3] = fmaf(s, c0.w, a[ 3]);
        a[ 4] = fmaf(s, c1.x, a[ 4]); a[ 5] = fmaf(s, c1.y, a[ 5]);
        a[ 6] = fmaf(s, c1.z, a[ 6]); a[ 7] = fmaf(s, c1.w, a[ 7]);
        a[ 8] = fmaf(s, c2.x, a[ 8]); a[ 9] = fmaf(s, c2.y, a[ 9]);
        a[10] = fmaf(s, c2.z, a[10]); a[11] = fmaf(s, c2.w, a[11]);
        a[12] = fmaf(s, c3.x, a[12]); a[13] = fmaf(s, c3.y, a[13]);
        a[14] = fmaf(s, c3.z, a[14]); a[15] = fmaf(s, c3.w, a[15]);
    }
    __syncwarp();

    // -------------------- mask candidates (key = 0) -----------------------
    // All sums strictly positive -> float bits order-preserving as unsigned.
    unsigned ue[16];
    #pragma unroll
    for (int k = 0; k < 4; ++k) {
        unsigned wbits = sbm[warp][k * 4 + (lane >> 3)];
        unsigned sh = (lane & 7) * 4;
        #pragma unroll
        for (int j = 0; j < 4; ++j) {
            bool masked = (wbits >> (sh + j)) & 1u;
            ue[k * 4 + j] = masked ? 0u : __float_as_uint(a[k * 4 + j]);
        }
    }

    // ---------------- warp max key + nonzero count ------------------------
    unsigned mk = 0;
    int cnz = 0;
    #pragma unroll
    for (int j = 0; j < 16; ++j) { mk = max(mk, ue[j]); cnz += (ue[j] != 0u); }
    #pragma unroll
    for (int o = 16; o > 0; o >>= 1)
        mk = max(mk, __shfl_xor_sync(FULLMASK, mk, o));
    cnz = __reduce_add_sync(FULLMASK, cnz);

    // -------- Illinois regula-falsi threshold select (exact) --------------
    // invariants: count(>lo)=clo > 32, count(>hi)=chi < 32
    unsigned lo = 0, hi = mk, T = 0;
    int clo = cnz, chi = 0;
    bool exact = false;
    int sameside = 0;      // >0: last updates were lo-side; <0: hi-side
    #pragma unroll 1
    for (int it = 0; it < 64 && (hi - lo > 1u); ++it) {
        unsigned mid;
        if (sameside >= 2 || sameside <= -2) {
            mid = lo + ((hi - lo) >> 1);          // bisection rescue
            sameside = 0;
        } else {
            float flo = __uint_as_float(lo);
            float fhi = __uint_as_float(hi);
            float t = (float)(clo - 32) / (float)(clo - chi);
            mid = __float_as_uint(fmaf(t, fhi - flo, flo));
            if (mid <= lo) mid = lo + 1u;
            else if (mid >= hi) mid = hi - 1u;
        }
        int c = 0;
        #pragma unroll
        for (int j = 0; j < 16; ++j) c += (ue[j] > mid);
        c = __reduce_add_sync(FULLMASK, c);
        if (c == 32) { T = mid; exact = true; break; }
        if (c > 32) { lo = mid; clo = c; sameside = (sameside > 0) ? sameside + 1 : 1; }
        else        { hi = mid; chi = c; sameside = (sameside < 0) ? sameside - 1 : -1; }
    }

    // -------------------- compact the 32 winners --------------------------
    if (exact) {
        #pragma unroll
        for (int k = 0; k < 4; ++k)
            #pragma unroll
            for (int j = 0; j < 4; ++j) {
                unsigned u = ue[k * 4 + j];
                if (u > T) {
                    int p = atomicAdd(&scnt[warp], 1);
                    sval[warp][p] = __uint_as_float(u);
                    sidx[warp][p] = k * 128 + lane * 4 + j;
                }
            }
        __syncwarp();
    } else {
        // boundary key hi is the exact 32nd-largest; fill ties by smallest idx
        unsigned Th = hi;
        #pragma unroll
        for (int k = 0; k < 4; ++k)
            #pragma unroll
            for (int j = 0; j < 4; ++j) {
                unsigned u = ue[k * 4 + j];
                int e = k * 128 + lane * 4 + j;
                if (u > Th) {
                    int p = atomicAdd(&scnt[warp], 1);
                    sval[warp][p] = __uint_as_float(u);
                    sidx[warp][p] = e;
                } else if (u == Th) {
                    int q = atomicAdd(&seqcnt[warp], 1);
                    if (q < 64) seqe[warp][q] = e;
                }
            }
        __syncwarp();
        int m = scnt[warp];
        int need = 32 - m;
        int qn = min(seqcnt[warp], 64);
        if (lane == 0) {  // serial, rare
            for (int t = 0; t < need; ++t) {
                int best = 0x7FFFFFFF, bj = -1;
                for (int j2 = 0; j2 < qn; ++j2)
                    if (seqe[warp][j2] < best) { best = seqe[warp][j2]; bj = j2; }
                sval[warp][m + t] = __uint_as_float(Th);
                sidx[warp][m + t] = best;
                if (bj >= 0) seqe[warp][bj] = 0x7FFFFFFF;
            }
        }
        __syncwarp();
    }

    float v = sval[warp][lane];
    int   e = sidx[warp][lane];

    // -------------------- bitonic sort 32 (desc value, asc index) ---------
    #pragma unroll
    for (int k = 2; k <= 32; k <<= 1) {
        #pragma unroll
        for (int j = k >> 1; j > 0; j >>= 1) {
            float ov = __shfl_xor_sync(FULLMASK, v, j);
            int   oe = __shfl_xor_sync(FULLMASK, e, j);
            bool lower   = (lane & j) == 0;
            bool dirDesc = (lane & k) == 0;
            bool otherBetter = (ov > v) || (ov == v && oe < e);
            bool take = (dirDesc == lower) ? otherBetter : !otherBetter;
            if (take) { v = ov; e = oe; }
        }
    }

    // -------------------- write output ------------------------------------
    const long long n = (long long)B * 64;
    if (mode == 0) {
        float* o = (float*)outp;
        o[b * 64 + lane]          = (float)myid;
        o[b * 64 + 32 + lane]     = (float)e;
        o[n + b * 64 + lane]      = mys;
        o[n + b * 64 + 32 + lane] = v;
    } else if (mode == 1) {
        long long* oid = (long long*)outp;
        float* osc = (float*)((char*)outp + n * 8);
        oid[b * 64 + lane]      = (long long)myid;
        oid[b * 64 + 32 + lane] = (long long)e;
        osc[b * 64 + lane]      = mys;
        osc[b * 64 + 32 + lane] = v;
    } else if (mode == 2) {
        int* oid = (int*)outp;
        float* osc = (float*)((char*)outp + n * 4);
        oid[b * 64 + lane]      = myid;
        oid[b * 64 + 32 + lane] = e;
        osc[b * 64 + lane]      = mys;
        osc[b * 64 + 32 + lane] = v;
    } else {
        double* o = (double*)outp;
        o[b * 64 + lane]          = (double)myid;
        o[b * 64 + 32 + lane]     = (double)e;
        o[n + b * 64 + lane]      = (double)mys;
        o[n + b * 64 + 32 + lane] = (double)v;
    }
}

// ---------------------------------------------------------------------------
extern "C" void kernel_launch(void* const* d_in, const int* in_sizes, int n_in,
                              void* d_out, int out_size) {
    const void*  ids    = d_in[0];
    const float* scores = (const float*)d_in[1];
    const float* cooc   = (const float*)d_in[2];

    const int B = in_sizes[0] / 32;
    const long long n = (long long)B * 64;
    const long long S = (long long)out_size;

    int mode;
    if      (S == 2 * n)                                  mode = 0; // f32 concat
    else if (S == 3 * n || S == 12 * n || 2 * S == 3 * n) mode = 1; // i64+f32 raw
    else if (S == 8 * n)                                  mode = 2; // i32+f32 raw
    else if (S == 4 * n)                                  mode = 3; // f64 concat
    else                                                  mode = 0; // safest

    k_detect<<<1, 128>>>((const unsigned*)ids, 1024);
    k_main<<<(B + WARPS - 1) / WARPS, 128>>>(ids, scores, cooc, d_out, B, mode);
}

// round 10
// speedup vs baseline: 1.2257x; 1.0067x over previous
#include <cuda_runtime.h>
#include <cstdint>

#define FULLMASK 0xFFFFFFFFu

// ---------------------------------------------------------------------------
// One warp per batch row.
//   e-mapping: element e = k*128 + lane*4 + j  (k 0..3, j 0..3)
// FP-order emulation of reference (scatter-add -> dense @ cooc):
//   duplicates combined first; ascending-id fused-FMA accumulation.
// Top-32 select: Illinois regula-falsi on float-interpreted keys (exact).
// Ids dtype (int64 vs int32) detected per-warp from the row's own words:
//   int64 LE with values<512 -> odd 32-bit words all zero.
// ---------------------------------------------------------------------------
constexpr int WARPS = 2;

__global__ __launch_bounds__(64, 21)
void k_main(const void* __restrict__ idsraw,
            const float* __restrict__ scores,
            const float* __restrict__ cooc,
            void* __restrict__ outp, int B, int mode)
{
    __shared__ unsigned sbm[WARPS][16];   // 512-bit candidate bitmap per row
    __shared__ float    sval[WARPS][32];
    __shared__ int      sidx[WARPS][32];
    __shared__ int      scnt[WARPS];
    __shared__ int      seqcnt[WARPS];
    __shared__ int      seqe[WARPS][64];

    const int warp = threadIdx.x >> 5;
    const int lane = threadIdx.x & 31;
    const long long b = (long long)blockIdx.x * WARPS + warp;
    if (b >= B) return;

    // ---- inline dtype detect + id load (valid under both dtypes) ---------
    unsigned w32 = ((const unsigned*)idsraw)[b * 32 + lane];
    unsigned oddnz = __ballot_sync(FULLMASK, (lane & 1) && (w32 != 0u));
    int myid;
    if (oddnz == 0u) myid = (int)((const long long*)idsraw)[b * 32 + lane];
    else             myid = (int)w32;
    const float mys = scores[b * 32 + lane];

    if (lane < 16) sbm[warp][lane] = 0u;
    if (lane == 0) { scnt[warp] = 0; seqcnt[warp] = 0; }
    __syncwarp();
    atomicOr(&sbm[warp][myid >> 5], 1u << (myid & 31));

    // ---- stable sort (id asc, occurrence asc) via bitonic on unique key ---
    int   skey = (myid << 5) | lane;     // unique -> stable
    float ssv  = mys;
    #pragma unroll
    for (int k = 2; k <= 32; k <<= 1) {
        #pragma unroll
        for (int j = k >> 1; j > 0; j >>= 1) {
            int   ok = __shfl_xor_sync(FULLMASK, skey, j);
            float os = __shfl_xor_sync(FULLMASK, ssv,  j);
            bool lower  = (lane & j) == 0;
            bool dirAsc = (lane & k) == 0;
            bool takeOther = (dirAsc == lower) ? (ok < skey) : (ok > skey);
            if (takeOther) { skey = ok; ssv = os; }
        }
    }
    const int sid = skey >> 5;           // ids ascending across lanes

    // ---- segmented inclusive scan: combine duplicate ids ------------------
    #pragma unroll
    for (int off = 1; off < 32; off <<= 1) {
        float up  = __shfl_up_sync(FULLMASK, ssv, off);
        int   uid = __shfl_up_sync(FULLMASK, sid, off);
        if (lane >= off && uid == sid) ssv += up;
    }
    int nid = __shfl_down_sync(FULLMASK, sid, 1);
    bool tail = (lane == 31) || (nid != sid);
    const float fs = tail ? ssv : 0.0f;  // fmaf(0,c,a)==a exactly

    // -------------------- sparse gather-accumulate (id-ascending) ---------
    float a[16];
    #pragma unroll
    for (int j = 0; j < 16; ++j) a[j] = 0.f;

    const float4* base4 = (const float4*)cooc;
    #pragma unroll 4
    for (int i = 0; i < 32; ++i) {
        int   id = __shfl_sync(FULLMASK, sid, i);
        float s  = __shfl_sync(FULLMASK, fs,  i);
        const float4* r = base4 + (size_t)id * 128 + lane;
        float4 c0 = __ldg(r);
        float4 c1 = __ldg(r + 32);
        float4 c2 = __ldg(r + 64);
        float4 c3 = __ldg(r + 96);
        a[ 0] = fmaf(s, c0.x, a[ 0]); a[ 1] = fmaf(s, c0.y, a[ 1]);
        a[ 2] = fmaf(s, c0.z, a[ 2]); a[ 3] = fmaf(s, c0.w, a[ 3]);
        a[ 4] = fmaf(s, c1.x, a[ 4]); a[ 5] = fmaf(s, c1.y, a[ 5]);
        a[ 6] = fmaf(s, c1.z, a[ 6]); a[ 7] = fmaf(s, c1.w, a[ 7]);
        a[ 8] = fmaf(s, c2.x, a[ 8]); a[ 9] = fmaf(s, c2.y, a[ 9]);
        a[10] = fmaf(s, c2.z, a[10]); a[11] = fmaf(s, c2.w, a[11]);
        a[12] = fmaf(s, c3.x, a[12]); a[13] = fmaf(s, c3.y, a[13]);
        a[14] = fmaf(s, c3.z, a[14]); a[15] = fmaf(s, c3.w, a[15]);
    }
    __syncwarp();

    // -------------------- mask candidates (key = 0) -----------------------
    // All sums strictly positive -> float bits order-preserving as unsigned.
    unsigned ue[16];
    #pragma unroll
    for (int k = 0; k < 4; ++k) {
        unsigned wbits = sbm[warp][k * 4 + (lane >> 3)];
        unsigned sh = (lane & 7) * 4;
        #pragma unroll
        for (int j = 0; j < 4; ++j) {
            bool masked = (wbits >> (sh + j)) & 1u;
            ue[k * 4 + j] = masked ? 0u : __float_as_uint(a[k * 4 + j]);
        }
    }

    // ---------------- warp max key + nonzero count ------------------------
    unsigned mk = 0;
    int cnz = 0;
    #pragma unroll
    for (int j = 0; j < 16; ++j) { mk = max(mk, ue[j]); cnz += (ue[j] != 0u); }
    #pragma unroll
    for (int o = 16; o > 0; o >>= 1)
        mk = max(mk, __shfl_xor_sync(FULLMASK, mk, o));
    cnz = __reduce_add_sync(FULLMASK, cnz);

    // -------- Illinois regula-falsi threshold select (exact) --------------
    // invariants: count(>lo)=clo > 32, count(>hi)=chi < 32
    unsigned lo = 0, hi = mk, T = 0;
    int clo = cnz, chi = 0;
    bool exact = false;
    int sameside = 0;      // >0: last updates were lo-side; <0: hi-side
    #pragma unroll 1
    for (int it = 0; it < 64 && (hi - lo > 1u); ++it) {
        unsigned mid;
        if (sameside >= 2 || sameside <= -2) {
            mid = lo + ((hi - lo) >> 1);          // bisection rescue
            sameside = 0;
        } else {
            float flo = __uint_as_float(lo);
            float fhi = __uint_as_float(hi);
            float t = (float)(clo - 32) / (float)(clo - chi);
            mid = __float_as_uint(fmaf(t, fhi - flo, flo));
            if (mid <= lo) mid = lo + 1u;
            else if (mid >= hi) mid = hi - 1u;
        }
        int c = 0;
        #pragma unroll
        for (int j = 0; j < 16; ++j) c += (ue[j] > mid);
        c = __reduce_add_sync(FULLMASK, c);
        if (c == 32) { T = mid; exact = true; break; }
        if (c > 32) { lo = mid; clo = c; sameside = (sameside > 0) ? sameside + 1 : 1; }
        else        { hi = mid; chi = c; sameside = (sameside < 0) ? sameside - 1 : -1; }
    }

    // -------------------- compact the 32 winners --------------------------
    if (exact) {
        #pragma unroll
        for (int k = 0; k < 4; ++k)
            #pragma unroll
            for (int j = 0; j < 4; ++j) {
                unsigned u = ue[k * 4 + j];
                if (u > T) {
                    int p = atomicAdd(&scnt[warp], 1);
                    sval[warp][p] = __uint_as_float(u);
                    sidx[warp][p] = k * 128 + lane * 4 + j;
                }
            }
        __syncwarp();
    } else {
        // boundary key hi is the exact 32nd-largest; fill ties by smallest idx
        unsigned Th = hi;
        #pragma unroll
        for (int k = 0; k < 4; ++k)
            #pragma unroll
            for (int j = 0; j < 4; ++j) {
                unsigned u = ue[k * 4 + j];
                int e = k * 128 + lane * 4 + j;
                if (u > Th) {
                    int p = atomicAdd(&scnt[warp], 1);
                    sval[warp][p] = __uint_as_float(u);
                    sidx[warp][p] = e;
                } else if (u == Th) {
                    int q = atomicAdd(&seqcnt[warp], 1);
                    if (q < 64) seqe[warp][q] = e;
                }
            }
        __syncwarp();
        int m = scnt[warp];
        int need = 32 - m;
        int qn = min(seqcnt[warp], 64);
        if (lane == 0) {  // serial, rare
            for (int t = 0; t < need; ++t) {
                int best = 0x7FFFFFFF, bj = -1;
                for (int j2 = 0; j2 < qn; ++j2)
                    if (seqe[warp][j2] < best) { best = seqe[warp][j2]; bj = j2; }
                sval[warp][m + t] = __uint_as_float(Th);
                sidx[warp][m + t] = best;
                if (bj >= 0) seqe[warp][bj] = 0x7FFFFFFF;
            }
        }
        __syncwarp();
    }

    float v = sval[warp][lane];
    int   e = sidx[warp][lane];

    // -------------------- bitonic sort 32 (desc value, asc index) ---------
    #pragma unroll
    for (int k = 2; k <= 32; k <<= 1) {
        #pragma unroll
        for (int j = k >> 1; j > 0; j >>= 1) {
            float ov = __shfl_xor_sync(FULLMASK, v, j);
            int   oe = __shfl_xor_sync(FULLMASK, e, j);
            bool lower   = (lane & j) == 0;
            bool dirDesc = (lane & k) == 0;
            bool otherBetter = (ov > v) || (ov == v && oe < e);
            bool take = (dirDesc == lower) ? otherBetter : !otherBetter;
            if (take) { v = ov; e = oe; }
        }
    }

    // -------------------- write output ------------------------------------
    const long long n = (long long)B * 64;
    if (mode == 0) {
        float* o = (float*)outp;
        o[b * 64 + lane]          = (float)myid;
        o[b * 64 + 32 + lane]     = (float)e;
        o[n + b * 64 + lane]      = mys;
        o[n + b * 64 + 32 + lane] = v;
    } else if (mode == 1) {
        long long* oid = (long long*)outp;
        float* osc = (float*)((char*)outp + n * 8);
        oid[b * 64 + lane]      = (long long)myid;
        oid[b * 64 + 32 + lane] = (long long)e;
        osc[b * 64 + lane]      = mys;
        osc[b * 64 + 32 + lane] = v;
    } else if (mode == 2) {
        int* oid = (int*)outp;
        float* osc = (float*)((char*)outp + n * 4);
        oid[b * 64 + lane]      = myid;
        oid[b * 64 + 32 + lane] = e;
        osc[b * 64 + lane]      = mys;
        osc[b * 64 + 32 + lane] = v;
    } else {
        double* o = (double*)outp;
        o[b * 64 + lane]          = (double)myid;
        o[b * 64 + 32 + lane]     = (double)e;
        o[n + b * 64 + lane]      = (double)mys;
        o[n + b * 64 + 32 + lane] = (double)v;
    }
}

// ---------------------------------------------------------------------------
extern "C" void kernel_launch(void* const* d_in, const int* in_sizes, int n_in,
                              void* d_out, int out_size) {
    const void*  ids    = d_in[0];
    const float* scores = (const float*)d_in[1];
    const float* cooc   = (const float*)d_in[2];

    const int B = in_sizes[0] / 32;
    const long long n = (long long)B * 64;
    const long long S = (long long)out_size;

    int mode;
    if      (S == 2 * n)                                  mode = 0; // f32 concat
    else if (S == 3 * n || S == 12 * n || 2 * S == 3 * n) mode = 1; // i64+f32 raw
    else if (S == 8 * n)                                  mode = 2; // i32+f32 raw
    else if (S == 4 * n)                                  mode = 3; // f64 concat
    else                                                  mode = 0; // safest

    k_main<<<(B + WARPS - 1) / WARPS, 32 * WARPS>>>(ids, scores, cooc, d_out, B, mode);
}